// round 1
// baseline (speedup 1.0000x reference)
#include <cuda_runtime.h>
#include <cuda_bf16.h>

#define W0 512
#define H0 512
#define BATCH 32

__global__ __launch_bounds__(128) void hdvlut_kernel(
    const int* __restrict__ img,
    const float4* __restrict__ hw,
    const float4* __restrict__ dw,
    const float4* __restrict__ vw,
    float* __restrict__ out)
{
    int x = blockIdx.x * blockDim.x + threadIdx.x;
    int y = blockIdx.y;
    int b = blockIdx.z;

    const int* im = img + (size_t)b * (H0 * W0);

    int xm = max(x - 1, 0), xp = min(x + 1, W0 - 1);
    int ym = max(y - 1, 0), yp = min(y + 1, H0 - 1);

    int a   = __ldg(&im[y  * W0 + x ]);
    int vl  = __ldg(&im[y  * W0 + xm]);
    int vr  = __ldg(&im[y  * W0 + xp]);
    int vu  = __ldg(&im[ym * W0 + x ]);
    int vd  = __ldg(&im[yp * W0 + x ]);
    int vul = __ldg(&im[ym * W0 + xm]);
    int vur = __ldg(&im[ym * W0 + xp]);
    int vdl = __ldg(&im[yp * W0 + xm]);
    int vdr = __ldg(&im[yp * W0 + xp]);

    int base = a << 8;

    // 8 LUT gathers (float4 = the 2x2 sub-pixel weights, row-major u*2+v)
    float4 HR = __ldg(&hw[base | vr ]);   // h, r=0: right neighbor, idx s*2+t
    float4 HL = __ldg(&hw[base | vl ]);   // h, r=2: left,  idx (1-s)*2+(1-t)
    float4 VD = __ldg(&vw[base | vd ]);   // v, r=0: down,  idx s*2+t
    float4 VU = __ldg(&vw[base | vu ]);   // v, r=2: up,    idx (1-s)*2+(1-t)
    float4 DR = __ldg(&dw[base | vdr]);   // d, r=0: down-right, idx s*2+t
    float4 DL = __ldg(&dw[base | vdl]);   // d, r=1: down-left,  idx (1-t)*2+s
    float4 UL = __ldg(&dw[base | vul]);   // d, r=2: up-left,    idx (1-s)*2+(1-t)
    float4 UR = __ldg(&dw[base | vur]);   // d, r=3: up-right,   idx t*2+(1-s)

    // s=0,t=0
    float o00 = HR.x + HL.w + VD.x + VU.w + DR.x + DL.z + UL.w + UR.y;
    // s=0,t=1
    float o01 = HR.y + HL.z + VD.y + VU.z + DR.y + DL.x + UL.z + UR.w;
    // s=1,t=0
    float o10 = HR.z + HL.y + VD.z + VU.y + DR.z + DL.w + UL.y + UR.x;
    // s=1,t=1
    float o11 = HR.w + HL.x + VD.w + VU.x + DR.w + DL.y + UL.x + UR.z;

    size_t obase = (size_t)b * (2 * H0) * (2 * W0) + (size_t)(2 * y) * (2 * W0) + 2 * x;
    float2* orow = reinterpret_cast<float2*>(out + obase);
    orow[0]  = make_float2(0.5f * o00, 0.5f * o01);
    orow[W0] = make_float2(0.5f * o10, 0.5f * o11);   // next output row: 2*W0 floats = W0 float2
}

extern "C" void kernel_launch(void* const* d_in, const int* in_sizes, int n_in,
                              void* d_out, int out_size)
{
    const int*    img = (const int*)d_in[0];
    const float4* hw  = (const float4*)d_in[1];
    const float4* dw  = (const float4*)d_in[2];
    const float4* vw  = (const float4*)d_in[3];
    float*        out = (float*)d_out;

    dim3 block(128, 1, 1);
    dim3 grid(W0 / 128, H0, BATCH);
    hdvlut_kernel<<<grid, block>>>(img, hw, dw, vw, out);
}

// round 2
// speedup vs baseline: 1.3753x; 1.3753x over previous
#include <cuda_runtime.h>
#include <cuda_fp16.h>

#define W0 512
#define H0 512
#define BATCH 32

// Fused pair tables: entry e = p*256+q holds 8 halves:
//   [0..3] = 0.5 * T[p*256+q]  ("self")
//   [4..7] = 0.5 * T[q*256+p]  ("other")
__device__ uint4 g_H2[65536];
__device__ uint4 g_V2[65536];
__device__ uint4 g_D2[65536];

static __device__ __forceinline__ unsigned pack_h2(float a, float b) {
    __half2 h = __floats2half2_rn(a, b);
    return *reinterpret_cast<unsigned*>(&h);
}

__global__ void prep_kernel(const float4* __restrict__ hw,
                            const float4* __restrict__ dw,
                            const float4* __restrict__ vw)
{
    int e = blockIdx.x * blockDim.x + threadIdx.x;   // p*256 + q
    int p = e >> 8, q = e & 255;
    int et = (q << 8) | p;

    {
        float4 s = hw[e], o = hw[et];
        uint4 u;
        u.x = pack_h2(0.5f * s.x, 0.5f * s.y);
        u.y = pack_h2(0.5f * s.z, 0.5f * s.w);
        u.z = pack_h2(0.5f * o.x, 0.5f * o.y);
        u.w = pack_h2(0.5f * o.z, 0.5f * o.w);
        g_H2[e] = u;
    }
    {
        float4 s = vw[e], o = vw[et];
        uint4 u;
        u.x = pack_h2(0.5f * s.x, 0.5f * s.y);
        u.y = pack_h2(0.5f * s.z, 0.5f * s.w);
        u.z = pack_h2(0.5f * o.x, 0.5f * o.y);
        u.w = pack_h2(0.5f * o.z, 0.5f * o.w);
        g_V2[e] = u;
    }
    {
        float4 s = dw[e], o = dw[et];
        uint4 u;
        u.x = pack_h2(0.5f * s.x, 0.5f * s.y);
        u.y = pack_h2(0.5f * s.z, 0.5f * s.w);
        u.z = pack_h2(0.5f * o.x, 0.5f * o.y);
        u.w = pack_h2(0.5f * o.z, 0.5f * o.w);
        g_D2[e] = u;
    }
}

static __device__ __forceinline__ void unpack8(uint4 u, float f[8]) {
    float2 a = __half22float2(*reinterpret_cast<__half2*>(&u.x));
    float2 b = __half22float2(*reinterpret_cast<__half2*>(&u.y));
    float2 c = __half22float2(*reinterpret_cast<__half2*>(&u.z));
    float2 d = __half22float2(*reinterpret_cast<__half2*>(&u.w));
    f[0] = a.x; f[1] = a.y; f[2] = b.x; f[3] = b.y;
    f[4] = c.x; f[5] = c.y; f[6] = d.x; f[7] = d.y;
}

// Each thread: 2-wide x 4-tall pixel tile at (x0, y0).
// Local img block v[6][4] covers rows y0-1..y0+4, cols x0-1..x0+2 (clamped).
// Pixel (r, c) in tile = local (iy=r+1, j=c+1).
__global__ __launch_bounds__(128) void hdvlut_kernel(
    const int* __restrict__ img,
    float* __restrict__ out)
{
    int x0 = (blockIdx.x * blockDim.x + threadIdx.x) * 2;
    int y0 = blockIdx.y * 4;
    int b  = blockIdx.z;

    const int* im = img + (size_t)b * (H0 * W0);

    int xs[4], ys[6];
#pragma unroll
    for (int i = 0; i < 4; i++) xs[i] = min(max(x0 - 1 + i, 0), W0 - 1);
#pragma unroll
    for (int i = 0; i < 6; i++) ys[i] = min(max(y0 - 1 + i, 0), H0 - 1);

    int v[6][4];
#pragma unroll
    for (int r = 0; r < 6; r++)
#pragma unroll
        for (int c = 0; c < 4; c++)
            v[r][c] = __ldg(&im[ys[r] * W0 + xs[c]]);

    float acc[4][2][4];
#pragma unroll
    for (int r = 0; r < 4; r++)
#pragma unroll
        for (int c = 0; c < 2; c++)
#pragma unroll
            for (int w = 0; w < 4; w++) acc[r][c][w] = 0.0f;

    // ---- H sites: pixel rows iy=1..4, site cols j=0..2, pair (v[iy][j], v[iy][j+1])
    // self = HR of pixel local col j  (tile c=j-1), m = w
    // other= HL of pixel local col j+1 (tile c=j),  m = 3-w
#pragma unroll
    for (int iy = 1; iy <= 4; iy++) {
#pragma unroll
        for (int j = 0; j <= 2; j++) {
            uint4 u = __ldg(&g_H2[(v[iy][j] << 8) | v[iy][j + 1]]);
            float f[8]; unpack8(u, f);
            int r = iy - 1;
            if (j >= 1) {
#pragma unroll
                for (int w = 0; w < 4; w++) acc[r][j - 1][w] += f[w];
            }
            if (j <= 1) {
#pragma unroll
                for (int w = 0; w < 4; w++) acc[r][j][3 - w] += f[4 + w];
            }
        }
    }

    // ---- V sites: pixel cols j=1..2, site rows iy=0..4, pair (v[iy][j], v[iy+1][j])
    // self = VD of pixel row iy (tile r=iy-1), m = w
    // other= VU of pixel row iy+1 (tile r=iy), m = 3-w
#pragma unroll
    for (int j = 1; j <= 2; j++) {
#pragma unroll
        for (int iy = 0; iy <= 4; iy++) {
            uint4 u = __ldg(&g_V2[(v[iy][j] << 8) | v[iy + 1][j]]);
            float f[8]; unpack8(u, f);
            int c = j - 1;
            if (iy >= 1) {
#pragma unroll
                for (int w = 0; w < 4; w++) acc[iy - 1][c][w] += f[w];
            }
            if (iy <= 3) {
#pragma unroll
                for (int w = 0; w < 4; w++) acc[iy][c][3 - w] += f[4 + w];
            }
        }
    }

    // ---- D main-diag sites: (iy, j), pair (v[iy][j], v[iy+1][j+1])
    // self = DR of pixel (iy, j)     [tile r=iy-1, c=j-1], m = w
    // other= UL of pixel (iy+1, j+1) [tile r=iy,   c=j],   m = 3-w
#pragma unroll
    for (int iy = 0; iy <= 4; iy++) {
#pragma unroll
        for (int j = 0; j <= 2; j++) {
            bool dr = (iy >= 1) && (j >= 1);
            bool ul = (iy <= 3) && (j <= 1);
            if (!dr && !ul) continue;
            uint4 u = __ldg(&g_D2[(v[iy][j] << 8) | v[iy + 1][j + 1]]);
            float f[8]; unpack8(u, f);
            if (dr) {
#pragma unroll
                for (int w = 0; w < 4; w++) acc[iy - 1][j - 1][w] += f[w];
            }
            if (ul) {
#pragma unroll
                for (int w = 0; w < 4; w++) acc[iy][j][3 - w] += f[4 + w];
            }
        }
    }

    // ---- D anti-diag sites: (iy, j), j=1..3, pair (v[iy][j], v[iy+1][j-1])
    // self = DL of pixel (iy, j)     [tile r=iy-1, c=j-1]: m map [1,3,0,2]
    // other= UR of pixel (iy+1, j-1) [tile r=iy,   c=j-2]: m map [2,0,3,1]
#pragma unroll
    for (int iy = 0; iy <= 4; iy++) {
#pragma unroll
        for (int j = 1; j <= 3; j++) {
            bool dl = (iy >= 1) && (j <= 2);
            bool ur = (iy <= 3) && (j >= 2);
            if (!dl && !ur) continue;
            uint4 u = __ldg(&g_D2[(v[iy][j] << 8) | v[iy + 1][j - 1]]);
            float f[8]; unpack8(u, f);
            if (dl) {
                int r = iy - 1, c = j - 1;
                acc[r][c][1] += f[0];
                acc[r][c][3] += f[1];
                acc[r][c][0] += f[2];
                acc[r][c][2] += f[3];
            }
            if (ur) {
                int r = iy, c = j - 2;
                acc[r][c][2] += f[4];
                acc[r][c][0] += f[5];
                acc[r][c][3] += f[6];
                acc[r][c][1] += f[7];
            }
        }
    }

    // ---- Store: 8 output rows x 4 floats, coalesced float4
    size_t ob = (size_t)b * (2 * H0) * (2 * W0);
#pragma unroll
    for (int r = 0; r < 4; r++) {
#pragma unroll
        for (int s = 0; s < 2; s++) {
            float4 o = make_float4(acc[r][0][s * 2 + 0], acc[r][0][s * 2 + 1],
                                   acc[r][1][s * 2 + 0], acc[r][1][s * 2 + 1]);
            size_t off = ob + (size_t)(2 * (y0 + r) + s) * (2 * W0) + 2 * x0;
            *reinterpret_cast<float4*>(out + off) = o;
        }
    }
}

extern "C" void kernel_launch(void* const* d_in, const int* in_sizes, int n_in,
                              void* d_out, int out_size)
{
    const int*    img = (const int*)d_in[0];
    const float4* hw  = (const float4*)d_in[1];
    const float4* dw  = (const float4*)d_in[2];
    const float4* vw  = (const float4*)d_in[3];
    float*        out = (float*)d_out;

    prep_kernel<<<256, 256>>>(hw, dw, vw);

    dim3 block(128, 1, 1);
    dim3 grid((W0 / 2) / 128, H0 / 4, BATCH);
    hdvlut_kernel<<<grid, block>>>(img, out);
}

// round 3
// speedup vs baseline: 1.5346x; 1.1158x over previous
#include <cuda_runtime.h>
#include <cuda_fp16.h>

#define W0 512
#define H0 512
#define BATCH 32

// Fused pair tables: entry e = p*256+q holds 8 halves:
//   [0..3] = 0.5 * T[p*256+q]  ("self")
//   [4..7] = 0.5 * T[q*256+p]  ("other")
__device__ uint4 g_H2[65536];
__device__ uint4 g_V2[65536];
__device__ uint4 g_D2[65536];

static __device__ __forceinline__ unsigned pack_h2(float a, float b) {
    __half2 h = __floats2half2_rn(a, b);
    return *reinterpret_cast<unsigned*>(&h);
}

__global__ void prep_kernel(const float4* __restrict__ hw,
                            const float4* __restrict__ dw,
                            const float4* __restrict__ vw)
{
    int e = blockIdx.x * blockDim.x + threadIdx.x;   // p*256 + q
    int p = e >> 8, q = e & 255;
    int et = (q << 8) | p;
    {
        float4 s = hw[e], o = hw[et];
        uint4 u;
        u.x = pack_h2(0.5f * s.x, 0.5f * s.y);
        u.y = pack_h2(0.5f * s.z, 0.5f * s.w);
        u.z = pack_h2(0.5f * o.x, 0.5f * o.y);
        u.w = pack_h2(0.5f * o.z, 0.5f * o.w);
        g_H2[e] = u;
    }
    {
        float4 s = vw[e], o = vw[et];
        uint4 u;
        u.x = pack_h2(0.5f * s.x, 0.5f * s.y);
        u.y = pack_h2(0.5f * s.z, 0.5f * s.w);
        u.z = pack_h2(0.5f * o.x, 0.5f * o.y);
        u.w = pack_h2(0.5f * o.z, 0.5f * o.w);
        g_V2[e] = u;
    }
    {
        float4 s = dw[e], o = dw[et];
        uint4 u;
        u.x = pack_h2(0.5f * s.x, 0.5f * s.y);
        u.y = pack_h2(0.5f * s.z, 0.5f * s.w);
        u.z = pack_h2(0.5f * o.x, 0.5f * o.y);
        u.w = pack_h2(0.5f * o.z, 0.5f * o.w);
        g_D2[e] = u;
    }
}

// ---- accumulation helpers (x,y are packed half2 pairs = 4 weights w=0..3) ----
static __device__ __forceinline__ void acc_fwd(float* a, unsigned x, unsigned y) {
    // a[w] += f[w]
    float2 p = __half22float2(*reinterpret_cast<__half2*>(&x));
    float2 q = __half22float2(*reinterpret_cast<__half2*>(&y));
    a[0] += p.x; a[1] += p.y; a[2] += q.x; a[3] += q.y;
}
static __device__ __forceinline__ void acc_rev(float* a, unsigned x, unsigned y) {
    // a[3-w] += f[w]
    float2 p = __half22float2(*reinterpret_cast<__half2*>(&x));
    float2 q = __half22float2(*reinterpret_cast<__half2*>(&y));
    a[3] += p.x; a[2] += p.y; a[1] += q.x; a[0] += q.y;
}
static __device__ __forceinline__ void acc_dl(float* a, unsigned x, unsigned y) {
    // map [1,3,0,2]
    float2 p = __half22float2(*reinterpret_cast<__half2*>(&x));
    float2 q = __half22float2(*reinterpret_cast<__half2*>(&y));
    a[1] += p.x; a[3] += p.y; a[0] += q.x; a[2] += q.y;
}
static __device__ __forceinline__ void acc_ur(float* a, unsigned x, unsigned y) {
    // map [2,0,3,1]
    float2 p = __half22float2(*reinterpret_cast<__half2*>(&x));
    float2 q = __half22float2(*reinterpret_cast<__half2*>(&y));
    a[2] += p.x; a[0] += p.y; a[3] += q.x; a[1] += q.y;
}

// Each thread: 2-wide x 4-tall pixel tile. Lanes own horizontally adjacent
// tiles; left-boundary pair sites are received from lane-1 via shfl_up
// (lane 0 gathers its own).
__global__ __launch_bounds__(128) void hdvlut_kernel(
    const int* __restrict__ img,
    float* __restrict__ out)
{
    int lane = threadIdx.x & 31;
    int x0 = (blockIdx.x * blockDim.x + threadIdx.x) * 2;
    int y0 = blockIdx.y * 4;
    int b  = blockIdx.z;

    const int* im = img + (size_t)b * (H0 * W0);

    int xs[4], ys[6];
#pragma unroll
    for (int i = 0; i < 4; i++) xs[i] = min(max(x0 - 1 + i, 0), W0 - 1);
#pragma unroll
    for (int i = 0; i < 6; i++) ys[i] = min(max(y0 - 1 + i, 0), H0 - 1);

    int v[6][4];
#pragma unroll
    for (int r = 0; r < 6; r++)
#pragma unroll
        for (int c = 0; c < 4; c++)
            v[r][c] = __ldg(&im[ys[r] * W0 + xs[c]]);

    float acc[4][2][4];
#pragma unroll
    for (int r = 0; r < 4; r++)
#pragma unroll
        for (int c = 0; c < 2; c++)
#pragma unroll
            for (int w = 0; w < 4; w++) acc[r][c][w] = 0.0f;

    const unsigned FULL = 0xFFFFFFFFu;

    // ---- H sites (rows iy=1..4): gather j=1,2; receive j=0 from left lane
#pragma unroll
    for (int iy = 1; iy <= 4; iy++) {
        int r = iy - 1;
        uint4 u1 = __ldg(&g_H2[(v[iy][1] << 8) | v[iy][2]]);
        uint4 u2 = __ldg(&g_H2[(v[iy][2] << 8) | v[iy][3]]);
        acc_fwd(acc[r][0], u1.x, u1.y);     // HR of pixel c=0
        acc_rev(acc[r][1], u1.z, u1.w);     // HL of pixel c=1
        acc_fwd(acc[r][1], u2.x, u2.y);     // HR of pixel c=1
        unsigned ox = __shfl_up_sync(FULL, u2.z, 1);
        unsigned oy = __shfl_up_sync(FULL, u2.w, 1);
        if (lane == 0) {
            uint4 u0 = __ldg(&g_H2[(v[iy][0] << 8) | v[iy][1]]);
            ox = u0.z; oy = u0.w;
        }
        acc_rev(acc[r][0], ox, oy);         // HL of pixel c=0
    }

    // ---- V sites (cols j=1,2; iy=0..4): no horizontal sharing
#pragma unroll
    for (int iy = 0; iy <= 4; iy++) {
        uint4 u = __ldg(&g_V2[(v[iy][1] << 8) | v[iy + 1][1]]);
        if (iy >= 1) acc_fwd(acc[iy - 1][0], u.x, u.y);   // VD
        if (iy <= 3) acc_rev(acc[iy][0], u.z, u.w);       // VU
        uint4 w2 = __ldg(&g_V2[(v[iy][2] << 8) | v[iy + 1][2]]);
        if (iy >= 1) acc_fwd(acc[iy - 1][1], w2.x, w2.y);
        if (iy <= 3) acc_rev(acc[iy][1], w2.z, w2.w);
    }

    // ---- D main-diag sites (pair (v[iy][j], v[iy+1][j+1])): gather j=1,2; receive j=0
#pragma unroll
    for (int iy = 0; iy <= 4; iy++) {
        uint4 u1 = __ldg(&g_D2[(v[iy][1] << 8) | v[iy + 1][2]]);
        if (iy >= 1) acc_fwd(acc[iy - 1][0], u1.x, u1.y); // DR of (iy-1, c=0)
        if (iy <= 3) acc_rev(acc[iy][1], u1.z, u1.w);     // UL of (iy,   c=1)
        uint4 u2 = __ldg(&g_D2[(v[iy][2] << 8) | v[iy + 1][3]]);
        if (iy >= 1) acc_fwd(acc[iy - 1][1], u2.x, u2.y); // DR of (iy-1, c=1)
        if (iy <= 3) {
            unsigned ox = __shfl_up_sync(FULL, u2.z, 1);
            unsigned oy = __shfl_up_sync(FULL, u2.w, 1);
            if (lane == 0) {
                uint4 u0 = __ldg(&g_D2[(v[iy][0] << 8) | v[iy + 1][1]]);
                ox = u0.z; oy = u0.w;
            }
            acc_rev(acc[iy][0], ox, oy);                  // UL of (iy, c=0)
        }
    }

    // ---- D anti-diag sites (pair (v[iy][j], v[iy+1][j-1])): gather j=2,3; receive j=1
#pragma unroll
    for (int iy = 0; iy <= 4; iy++) {
        uint4 u2 = __ldg(&g_D2[(v[iy][2] << 8) | v[iy + 1][1]]);
        if (iy >= 1) acc_dl(acc[iy - 1][1], u2.x, u2.y);  // DL of (iy-1, c=1)
        if (iy <= 3) acc_ur(acc[iy][0], u2.z, u2.w);      // UR of (iy,   c=0)
        uint4 u3 = __ldg(&g_D2[(v[iy][3] << 8) | v[iy + 1][2]]);
        if (iy <= 3) acc_ur(acc[iy][1], u3.z, u3.w);      // UR of (iy,   c=1)
        if (iy >= 1) {
            unsigned sx = __shfl_up_sync(FULL, u3.x, 1);
            unsigned sy = __shfl_up_sync(FULL, u3.y, 1);
            if (lane == 0) {
                uint4 u1 = __ldg(&g_D2[(v[iy][1] << 8) | v[iy + 1][0]]);
                sx = u1.x; sy = u1.y;
            }
            acc_dl(acc[iy - 1][0], sx, sy);               // DL of (iy-1, c=0)
        }
    }

    // ---- Store: 8 output rows x 4 floats, coalesced float4
    size_t ob = (size_t)b * (2 * H0) * (2 * W0);
#pragma unroll
    for (int r = 0; r < 4; r++) {
#pragma unroll
        for (int s = 0; s < 2; s++) {
            float4 o = make_float4(acc[r][0][s * 2 + 0], acc[r][0][s * 2 + 1],
                                   acc[r][1][s * 2 + 0], acc[r][1][s * 2 + 1]);
            size_t off = ob + (size_t)(2 * (y0 + r) + s) * (2 * W0) + 2 * x0;
            *reinterpret_cast<float4*>(out + off) = o;
        }
    }
}

extern "C" void kernel_launch(void* const* d_in, const int* in_sizes, int n_in,
                              void* d_out, int out_size)
{
    const int*    img = (const int*)d_in[0];
    const float4* hw  = (const float4*)d_in[1];
    const float4* dw  = (const float4*)d_in[2];
    const float4* vw  = (const float4*)d_in[3];
    float*        out = (float*)d_out;

    prep_kernel<<<256, 256>>>(hw, dw, vw);

    dim3 block(128, 1, 1);
    dim3 grid((W0 / 2) / 128, H0 / 4, BATCH);
    hdvlut_kernel<<<grid, block>>>(img, out);
}